// round 7
// baseline (speedup 1.0000x reference)
#include <cuda_runtime.h>
#include <math.h>
#include <stdint.h>

// Problem constants
constexpr int cB   = 2;
constexpr int cS   = 2048;
constexpr int cD   = 1024;
constexpr int cH   = 16;
constexpr int cHKV = 4;
constexpr int cDK  = 64;
constexpr int cNKV = cHKV * cDK;   // 256
constexpr int cM   = cB * cS;      // 4096

// Scratch (no allocations allowed)
__device__ float g_qh [cB * cS * cD];
__device__ float g_kh [cB * cS * cNKV];
__device__ float g_vh [cB * cS * cNKV];
__device__ float g_att[cB * cS * cD];

// ---------------------------------------------------------------------------
// tf32 helpers
// ---------------------------------------------------------------------------
__device__ __forceinline__ unsigned f2tf(float f) {
    unsigned u;
    asm("cvt.rna.tf32.f32 %0, %1;" : "=r"(u) : "f"(f));
    return u;
}

// D = A(16x8,row) @ B(8x8,col) + C, tf32 in / f32 out
__device__ __forceinline__ void mma_tf32(float d[4], const unsigned a[4],
                                         unsigned b0, unsigned b1) {
    asm("mma.sync.aligned.m16n8k8.row.col.f32.tf32.tf32.f32 "
        "{%0,%1,%2,%3}, {%4,%5,%6,%7}, {%8,%9}, {%0,%1,%2,%3};"
        : "+f"(d[0]), "+f"(d[1]), "+f"(d[2]), "+f"(d[3])
        : "r"(a[0]), "r"(a[1]), "r"(a[2]), "r"(a[3]), "r"(b0), "r"(b1));
}

// ---------------------------------------------------------------------------
// GEMM + bias via tf32 mma: C[M,N] = A[M,K] @ W[K,N] + bias[N]
// 128x128 block tile, BK=16, 256 threads = 8 warps (2m x 4n), warp tile 64x32.
// Double-buffered smem; fragment LDS bank-conflict-free by padding.
// Requires M%128==0, N%128==0, K%16==0.
// ---------------------------------------------------------------------------
__global__ __launch_bounds__(256)
void gemm_mma(const float* __restrict__ A, const float* __restrict__ W,
              const float* __restrict__ bias, float* __restrict__ C,
              int M, int N, int K) {
    __shared__ __align__(16) unsigned As[2][128][20];   // [m][k], stride 20
    __shared__ __align__(16) unsigned Bs[2][16][136];   // [k][n], stride 136

    const int tid  = threadIdx.x;
    const int w    = tid >> 5;
    const int lane = tid & 31;
    const int g    = lane >> 2;     // groupID 0..7
    const int tg   = lane & 3;      // threadInGroup 0..3
    const int wm   = w & 1;         // 0..1  -> m half (64 rows)
    const int wn   = w >> 1;        // 0..3  -> n quarter (32 cols)
    const int m0   = blockIdx.y * 128;
    const int n0   = blockIdx.x * 128;

    // Load mappings
    const int a_row = tid >> 1;            // 0..127
    const int a_kq  = (tid & 1) * 8;       // 0 or 8
    const int b_row = tid >> 4;            // 0..15
    const int b_col = (tid & 15) * 4;      // 0..60

    const float* Ap = A + (size_t)(m0 + a_row) * K + a_kq;
    const float* Bp0 = W + (size_t)b_row * N + n0 + b_col;
    const float* Bp1 = Bp0 + 64;

    float acc[4][4][4];   // [mi][ni][frag]
    #pragma unroll
    for (int mi = 0; mi < 4; mi++)
        #pragma unroll
        for (int ni = 0; ni < 4; ni++)
            #pragma unroll
            for (int f = 0; f < 4; f++) acc[mi][ni][f] = 0.f;

    const int nt = K / 16;

    // Prologue: tile 0 -> buffer 0
    {
        float4 a0 = *reinterpret_cast<const float4*>(Ap);
        float4 a1 = *reinterpret_cast<const float4*>(Ap + 4);
        float4 w0 = *reinterpret_cast<const float4*>(Bp0);
        float4 w1 = *reinterpret_cast<const float4*>(Bp1);
        uint4 ua0 = {f2tf(a0.x), f2tf(a0.y), f2tf(a0.z), f2tf(a0.w)};
        uint4 ua1 = {f2tf(a1.x), f2tf(a1.y), f2tf(a1.z), f2tf(a1.w)};
        uint4 uw0 = {f2tf(w0.x), f2tf(w0.y), f2tf(w0.z), f2tf(w0.w)};
        uint4 uw1 = {f2tf(w1.x), f2tf(w1.y), f2tf(w1.z), f2tf(w1.w)};
        *reinterpret_cast<uint4*>(&As[0][a_row][a_kq])     = ua0;
        *reinterpret_cast<uint4*>(&As[0][a_row][a_kq + 4]) = ua1;
        *reinterpret_cast<uint4*>(&Bs[0][b_row][b_col])      = uw0;
        *reinterpret_cast<uint4*>(&Bs[0][b_row][b_col + 64]) = uw1;
    }
    __syncthreads();

    for (int t = 0; t < nt; t++) {
        const int cur = t & 1;
        float4 a0, a1, w0, w1;
        if (t + 1 < nt) {
            const size_t ko = (size_t)(t + 1) * 16;
            a0 = *reinterpret_cast<const float4*>(Ap + ko);
            a1 = *reinterpret_cast<const float4*>(Ap + ko + 4);
            w0 = *reinterpret_cast<const float4*>(Bp0 + ko * N);
            w1 = *reinterpret_cast<const float4*>(Bp1 + ko * N);
        }

        #pragma unroll
        for (int kk = 0; kk < 2; kk++) {
            // A fragments: rows wm*64 + 16mi + g(+8), cols 8kk + tg(+4)
            unsigned af[4][4];
            #pragma unroll
            for (int mi = 0; mi < 4; mi++) {
                const int r = wm * 64 + 16 * mi + g;
                af[mi][0] = As[cur][r][8 * kk + tg];
                af[mi][1] = As[cur][r + 8][8 * kk + tg];
                af[mi][2] = As[cur][r][8 * kk + tg + 4];
                af[mi][3] = As[cur][r + 8][8 * kk + tg + 4];
            }
            // B fragments: rows 8kk + tg(+4), cols wn*32 + 8ni + g
            unsigned bf[4][2];
            #pragma unroll
            for (int ni = 0; ni < 4; ni++) {
                const int c = wn * 32 + 8 * ni + g;
                bf[ni][0] = Bs[cur][8 * kk + tg][c];
                bf[ni][1] = Bs[cur][8 * kk + tg + 4][c];
            }
            #pragma unroll
            for (int mi = 0; mi < 4; mi++)
                #pragma unroll
                for (int ni = 0; ni < 4; ni++)
                    mma_tf32(acc[mi][ni], af[mi], bf[ni][0], bf[ni][1]);
        }

        if (t + 1 < nt) {
            const int nxt = cur ^ 1;
            uint4 ua0 = {f2tf(a0.x), f2tf(a0.y), f2tf(a0.z), f2tf(a0.w)};
            uint4 ua1 = {f2tf(a1.x), f2tf(a1.y), f2tf(a1.z), f2tf(a1.w)};
            uint4 uw0 = {f2tf(w0.x), f2tf(w0.y), f2tf(w0.z), f2tf(w0.w)};
            uint4 uw1 = {f2tf(w1.x), f2tf(w1.y), f2tf(w1.z), f2tf(w1.w)};
            *reinterpret_cast<uint4*>(&As[nxt][a_row][a_kq])     = ua0;
            *reinterpret_cast<uint4*>(&As[nxt][a_row][a_kq + 4]) = ua1;
            *reinterpret_cast<uint4*>(&Bs[nxt][b_row][b_col])      = uw0;
            *reinterpret_cast<uint4*>(&Bs[nxt][b_row][b_col + 64]) = uw1;
        }
        __syncthreads();
    }

    // Epilogue: C fragments (rows ..+g, ..+g+8; cols ..+2tg, +2tg+1) + bias
    #pragma unroll
    for (int ni = 0; ni < 4; ni++) {
        const int col = n0 + wn * 32 + 8 * ni + 2 * tg;
        const float2 bv = *reinterpret_cast<const float2*>(&bias[col]);
        #pragma unroll
        for (int mi = 0; mi < 4; mi++) {
            const int r0 = m0 + wm * 64 + 16 * mi + g;
            float2 o0 = {acc[mi][ni][0] + bv.x, acc[mi][ni][1] + bv.y};
            float2 o1 = {acc[mi][ni][2] + bv.x, acc[mi][ni][3] + bv.y};
            *reinterpret_cast<float2*>(&C[(size_t)r0 * N + col])       = o0;
            *reinterpret_cast<float2*>(&C[(size_t)(r0 + 8) * N + col]) = o1;
        }
    }
}

// ---------------------------------------------------------------------------
// Causal GQA flash attention via tf32 mma.
// grid (S/64, H, B), 128 threads = 4 warps; warp w owns query rows 16w..16w+15.
// Q fragments register-resident (x 1/sqrt(dk)); K smem [key][dk] stride 68;
// V smem transposed [dk][key] stride 68 with the keys of every 8-group
// PERMUTED by sigma(s) = (s>>1)|((s&1)<<2). This makes the S C-fragment
// layout directly reusable as the P A-fragment for the PV mma (a = {c0,c2,
// c1,c3}) with no shuffles: A-col j reads key pi(j) = (j<4 ? 2j : 2j-7),
// and sigma = pi^-1. Softmax/masking are key-order invariant.
// ---------------------------------------------------------------------------
__global__ __launch_bounds__(128, 4)
void attn_mma(const float* __restrict__ qh, const float* __restrict__ kh,
              const float* __restrict__ vh, float* __restrict__ out) {
    __shared__ __align__(16) unsigned Ks[64][68];   // [key][dk] (also Q staging)
    __shared__ __align__(16) unsigned Vt[64][68];   // [dk][key-permuted]

    const int tid  = threadIdx.x;
    const int w    = tid >> 5;
    const int lane = tid & 31;
    const int g    = lane >> 2;
    const int tg   = lane & 3;
    const int bx   = blockIdx.x;
    const int h    = blockIdx.y;
    const int b    = blockIdx.z;
    const int kvh  = h >> 2;
    const int q0   = bx * 64;

    // Stage Q tile (rows q0..q0+63) into Ks, scaled, tf32
    if (tid < 64) {
        const float* qp = qh + ((size_t)(b * cS + q0 + tid)) * cD + h * cDK;
        #pragma unroll
        for (int i = 0; i < 16; i++) {
            float4 v = reinterpret_cast<const float4*>(qp)[i];
            uint4 u = {f2tf(v.x * 0.125f), f2tf(v.y * 0.125f),
                       f2tf(v.z * 0.125f), f2tf(v.w * 0.125f)};
            *reinterpret_cast<uint4*>(&Ks[tid][4 * i]) = u;
        }
    }
    __syncthreads();

    // Q A-fragments: 8 k-steps; rows 16w+g(+8), cols 8ks+tg(+4)
    unsigned qf[8][4];
    #pragma unroll
    for (int ks = 0; ks < 8; ks++) {
        qf[ks][0] = Ks[16 * w + g][8 * ks + tg];
        qf[ks][1] = Ks[16 * w + g + 8][8 * ks + tg];
        qf[ks][2] = Ks[16 * w + g][8 * ks + tg + 4];
        qf[ks][3] = Ks[16 * w + g + 8][8 * ks + tg + 4];
    }

    float O[8][4];
    #pragma unroll
    for (int ni = 0; ni < 8; ni++)
        #pragma unroll
        for (int f = 0; f < 4; f++) O[ni][f] = 0.f;
    float mr0 = -1e30f, mr1 = -1e30f;   // row maxima (rows g, g+8)
    float lr0 = 0.f, lr1 = 0.f;         // row sums

    for (int kt = 0; kt <= bx; kt++) {
        __syncthreads();   // previous tile compute done (also guards Q frag reads)
        // Load K/V tile: threads 0..63 -> V row (transposed + key-permuted),
        //                threads 64..127 -> K row (natural order).
        if (tid < 64) {
            const float* vp = vh + ((size_t)(b * cS + kt * 64 + tid)) * cNKV + kvh * cDK;
            // permuted column for this key within its 8-group
            const int scol = (tid & 56) | ((tid & 7) >> 1) | ((tid & 1) << 2);
            #pragma unroll
            for (int i = 0; i < 16; i++) {
                float4 v = reinterpret_cast<const float4*>(vp)[i];
                Vt[4 * i + 0][scol] = f2tf(v.x);
                Vt[4 * i + 1][scol] = f2tf(v.y);
                Vt[4 * i + 2][scol] = f2tf(v.z);
                Vt[4 * i + 3][scol] = f2tf(v.w);
            }
        } else {
            const int r = tid - 64;
            const float* kp = kh + ((size_t)(b * cS + kt * 64 + r)) * cNKV + kvh * cDK;
            #pragma unroll
            for (int i = 0; i < 16; i++) {
                float4 v = reinterpret_cast<const float4*>(kp)[i];
                uint4 u = {f2tf(v.x), f2tf(v.y), f2tf(v.z), f2tf(v.w)};
                *reinterpret_cast<uint4*>(&Ks[r][4 * i]) = u;
            }
        }
        __syncthreads();

        // S = Q @ K^T : 8 n-tiles of 8 keys
        float S[8][4];
        #pragma unroll
        for (int ni = 0; ni < 8; ni++) {
            S[ni][0] = S[ni][1] = S[ni][2] = S[ni][3] = 0.f;
            #pragma unroll
            for (int ks = 0; ks < 8; ks++) {
                unsigned b0 = Ks[8 * ni + g][8 * ks + tg];
                unsigned b1 = Ks[8 * ni + g][8 * ks + tg + 4];
                mma_tf32(S[ni], qf[ks], b0, b1);
            }
        }

        // Causal mask on diagonal tile (q0 == kt*64: compare in-tile indices)
        if (kt == bx) {
            const int r0 = 16 * w + g, r1 = r0 + 8;
            #pragma unroll
            for (int ni = 0; ni < 8; ni++) {
                const int c0 = 8 * ni + 2 * tg, c1 = c0 + 1;
                if (c0 > r0) S[ni][0] = -1e30f;
                if (c1 > r0) S[ni][1] = -1e30f;
                if (c0 > r1) S[ni][2] = -1e30f;
                if (c1 > r1) S[ni][3] = -1e30f;
            }
        }

        // Online softmax (rows g and g+8 per thread; quad butterfly)
        float mx0 = -1e30f, mx1 = -1e30f;
        #pragma unroll
        for (int ni = 0; ni < 8; ni++) {
            mx0 = fmaxf(mx0, fmaxf(S[ni][0], S[ni][1]));
            mx1 = fmaxf(mx1, fmaxf(S[ni][2], S[ni][3]));
        }
        mx0 = fmaxf(mx0, __shfl_xor_sync(0xffffffffu, mx0, 1));
        mx0 = fmaxf(mx0, __shfl_xor_sync(0xffffffffu, mx0, 2));
        mx1 = fmaxf(mx1, __shfl_xor_sync(0xffffffffu, mx1, 1));
        mx1 = fmaxf(mx1, __shfl_xor_sync(0xffffffffu, mx1, 2));

        const float mn0 = fmaxf(mr0, mx0), mn1 = fmaxf(mr1, mx1);
        const float c0 = __expf(mr0 - mn0), c1 = __expf(mr1 - mn1);
        mr0 = mn0; mr1 = mn1;

        float s0 = 0.f, s1 = 0.f;
        #pragma unroll
        for (int ni = 0; ni < 8; ni++) {
            float p0 = __expf(S[ni][0] - mn0);
            float p1 = __expf(S[ni][1] - mn0);
            float p2 = __expf(S[ni][2] - mn1);
            float p3 = __expf(S[ni][3] - mn1);
            s0 += p0 + p1;
            s1 += p2 + p3;
            // store tf32 bits of P in place
            S[ni][0] = __uint_as_float(f2tf(p0));
            S[ni][1] = __uint_as_float(f2tf(p1));
            S[ni][2] = __uint_as_float(f2tf(p2));
            S[ni][3] = __uint_as_float(f2tf(p3));
        }
        s0 += __shfl_xor_sync(0xffffffffu, s0, 1);
        s0 += __shfl_xor_sync(0xffffffffu, s0, 2);
        s1 += __shfl_xor_sync(0xffffffffu, s1, 1);
        s1 += __shfl_xor_sync(0xffffffffu, s1, 2);
        lr0 = lr0 * c0 + s0;
        lr1 = lr1 * c1 + s1;
        #pragma unroll
        for (int ni = 0; ni < 8; ni++) {
            O[ni][0] *= c0; O[ni][1] *= c0;
            O[ni][2] *= c1; O[ni][3] *= c1;
        }

        // O += P @ V : C-fragment of S reused directly as A-fragment
        // (keys permuted in Vt so no shuffle needed): a = {c0, c2, c1, c3}.
        #pragma unroll
        for (int ks = 0; ks < 8; ks++) {
            unsigned a[4];
            a[0] = __float_as_uint(S[ks][0]);
            a[1] = __float_as_uint(S[ks][2]);
            a[2] = __float_as_uint(S[ks][1]);
            a[3] = __float_as_uint(S[ks][3]);
            #pragma unroll
            for (int ni = 0; ni < 8; ni++) {
                unsigned b0 = Vt[8 * ni + g][8 * ks + tg];
                unsigned b1 = Vt[8 * ni + g][8 * ks + tg + 4];
                mma_tf32(O[ni], a, b0, b1);
            }
        }
    }

    // Normalize + store
    const float inv0 = 1.f / lr0, inv1 = 1.f / lr1;
    const int r0 = q0 + 16 * w + g;
    float* op0 = out + ((size_t)(b * cS + r0)) * cD + h * cDK;
    float* op1 = op0 + (size_t)8 * cD;
    #pragma unroll
    for (int ni = 0; ni < 8; ni++) {
        float2 o0 = {O[ni][0] * inv0, O[ni][1] * inv0};
        float2 o1 = {O[ni][2] * inv1, O[ni][3] * inv1};
        *reinterpret_cast<float2*>(op0 + 8 * ni + 2 * tg) = o0;
        *reinterpret_cast<float2*>(op1 + 8 * ni + 2 * tg) = o1;
    }
}

// ---------------------------------------------------------------------------
// Launch
// ---------------------------------------------------------------------------
extern "C" void kernel_launch(void* const* d_in, const int* in_sizes, int n_in,
                              void* d_out, int out_size) {
    const float* q  = (const float*)d_in[0];
    const float* k  = (const float*)d_in[1];
    const float* v  = (const float*)d_in[2];
    const float* Wq = (const float*)d_in[4];
    const float* bq = (const float*)d_in[5];
    const float* Wk = (const float*)d_in[6];
    const float* bk = (const float*)d_in[7];
    const float* Wv = (const float*)d_in[8];
    const float* bv = (const float*)d_in[9];
    const float* Wo = (const float*)d_in[10];
    const float* bo = (const float*)d_in[11];
    float* out = (float*)d_out;

    float *qh, *kh, *vh, *att;
    cudaGetSymbolAddress((void**)&qh,  g_qh);
    cudaGetSymbolAddress((void**)&kh,  g_kh);
    cudaGetSymbolAddress((void**)&vh,  g_vh);
    cudaGetSymbolAddress((void**)&att, g_att);

    gemm_mma<<<dim3(cD   / 128, cM / 128), 256>>>(q, Wq, bq, qh, cM, cD,   cD);
    gemm_mma<<<dim3(cNKV / 128, cM / 128), 256>>>(k, Wk, bk, kh, cM, cNKV, cD);
    gemm_mma<<<dim3(cNKV / 128, cM / 128), 256>>>(v, Wv, bv, vh, cM, cNKV, cD);

    attn_mma<<<dim3(cS / 64, cH, cB), 128>>>(qh, kh, vh, att);

    gemm_mma<<<dim3(cD / 128, cM / 128), 256>>>(att, Wo, bo, out, cM, cD, cD);
}

// round 10
// speedup vs baseline: 1.5177x; 1.5177x over previous
#include <cuda_runtime.h>
#include <math.h>
#include <stdint.h>

// Problem constants
constexpr int cB   = 2;
constexpr int cS   = 2048;
constexpr int cD   = 1024;
constexpr int cH   = 16;
constexpr int cHKV = 4;
constexpr int cDK  = 64;
constexpr int cNKV = cHKV * cDK;   // 256
constexpr int cM   = cB * cS;      // 4096

// Scratch (no allocations allowed)
__device__ float g_qh [cB * cS * cD];
__device__ float g_kh [cB * cS * cNKV];
__device__ float g_vh [cB * cS * cNKV];
__device__ float g_att[cB * cS * cD];

// ---------------------------------------------------------------------------
// tf32 helpers
// ---------------------------------------------------------------------------
__device__ __forceinline__ unsigned f2tf(float f) {
    unsigned u;
    asm("cvt.rna.tf32.f32 %0, %1;" : "=r"(u) : "f"(f));
    return u;
}

// D = A(16x8,row) @ B(8x8,col) + C, tf32 in / f32 out
__device__ __forceinline__ void mma_tf32(float d[4], const unsigned a[4],
                                         unsigned b0, unsigned b1) {
    asm("mma.sync.aligned.m16n8k8.row.col.f32.tf32.tf32.f32 "
        "{%0,%1,%2,%3}, {%4,%5,%6,%7}, {%8,%9}, {%0,%1,%2,%3};"
        : "+f"(d[0]), "+f"(d[1]), "+f"(d[2]), "+f"(d[3])
        : "r"(a[0]), "r"(a[1]), "r"(a[2]), "r"(a[3]), "r"(b0), "r"(b1));
}

// ---------------------------------------------------------------------------
// GEMM + bias via tf32 mma: C[M,N] = A[M,K] @ W[K,N] + bias[N]
// 128x128 block tile, BK=16, 256 threads = 8 warps (2m x 4n), warp tile 64x32.
// Double-buffered smem; fragment LDS bank-conflict-free by padding.
// Requires M%128==0, N%128==0, K%16==0.
// ---------------------------------------------------------------------------
__global__ __launch_bounds__(256)
void gemm_mma(const float* __restrict__ A, const float* __restrict__ W,
              const float* __restrict__ bias, float* __restrict__ C,
              int M, int N, int K) {
    __shared__ __align__(16) unsigned As[2][128][20];   // [m][k], stride 20
    __shared__ __align__(16) unsigned Bs[2][16][136];   // [k][n], stride 136

    const int tid  = threadIdx.x;
    const int w    = tid >> 5;
    const int lane = tid & 31;
    const int g    = lane >> 2;     // groupID 0..7
    const int tg   = lane & 3;      // threadInGroup 0..3
    const int wm   = w & 1;         // 0..1  -> m half (64 rows)
    const int wn   = w >> 1;        // 0..3  -> n quarter (32 cols)
    const int m0   = blockIdx.y * 128;
    const int n0   = blockIdx.x * 128;

    // Load mappings
    const int a_row = tid >> 1;            // 0..127
    const int a_kq  = (tid & 1) * 8;       // 0 or 8
    const int b_row = tid >> 4;            // 0..15
    const int b_col = (tid & 15) * 4;      // 0..60

    const float* Ap = A + (size_t)(m0 + a_row) * K + a_kq;
    const float* Bp0 = W + (size_t)b_row * N + n0 + b_col;
    const float* Bp1 = Bp0 + 64;

    float acc[4][4][4];   // [mi][ni][frag]
    #pragma unroll
    for (int mi = 0; mi < 4; mi++)
        #pragma unroll
        for (int ni = 0; ni < 4; ni++)
            #pragma unroll
            for (int f = 0; f < 4; f++) acc[mi][ni][f] = 0.f;

    const int nt = K / 16;

    // Prologue: tile 0 -> buffer 0
    {
        float4 a0 = *reinterpret_cast<const float4*>(Ap);
        float4 a1 = *reinterpret_cast<const float4*>(Ap + 4);
        float4 w0 = *reinterpret_cast<const float4*>(Bp0);
        float4 w1 = *reinterpret_cast<const float4*>(Bp1);
        uint4 ua0 = {f2tf(a0.x), f2tf(a0.y), f2tf(a0.z), f2tf(a0.w)};
        uint4 ua1 = {f2tf(a1.x), f2tf(a1.y), f2tf(a1.z), f2tf(a1.w)};
        uint4 uw0 = {f2tf(w0.x), f2tf(w0.y), f2tf(w0.z), f2tf(w0.w)};
        uint4 uw1 = {f2tf(w1.x), f2tf(w1.y), f2tf(w1.z), f2tf(w1.w)};
        *reinterpret_cast<uint4*>(&As[0][a_row][a_kq])     = ua0;
        *reinterpret_cast<uint4*>(&As[0][a_row][a_kq + 4]) = ua1;
        *reinterpret_cast<uint4*>(&Bs[0][b_row][b_col])      = uw0;
        *reinterpret_cast<uint4*>(&Bs[0][b_row][b_col + 64]) = uw1;
    }
    __syncthreads();

    for (int t = 0; t < nt; t++) {
        const int cur = t & 1;
        float4 a0, a1, w0, w1;
        if (t + 1 < nt) {
            const size_t ko = (size_t)(t + 1) * 16;
            a0 = *reinterpret_cast<const float4*>(Ap + ko);
            a1 = *reinterpret_cast<const float4*>(Ap + ko + 4);
            w0 = *reinterpret_cast<const float4*>(Bp0 + ko * N);
            w1 = *reinterpret_cast<const float4*>(Bp1 + ko * N);
        }

        #pragma unroll
        for (int kk = 0; kk < 2; kk++) {
            // A fragments: rows wm*64 + 16mi + g(+8), cols 8kk + tg(+4)
            unsigned af[4][4];
            #pragma unroll
            for (int mi = 0; mi < 4; mi++) {
                const int r = wm * 64 + 16 * mi + g;
                af[mi][0] = As[cur][r][8 * kk + tg];
                af[mi][1] = As[cur][r + 8][8 * kk + tg];
                af[mi][2] = As[cur][r][8 * kk + tg + 4];
                af[mi][3] = As[cur][r + 8][8 * kk + tg + 4];
            }
            // B fragments: rows 8kk + tg(+4), cols wn*32 + 8ni + g
            unsigned bf[4][2];
            #pragma unroll
            for (int ni = 0; ni < 4; ni++) {
                const int c = wn * 32 + 8 * ni + g;
                bf[ni][0] = Bs[cur][8 * kk + tg][c];
                bf[ni][1] = Bs[cur][8 * kk + tg + 4][c];
            }
            #pragma unroll
            for (int mi = 0; mi < 4; mi++)
                #pragma unroll
                for (int ni = 0; ni < 4; ni++)
                    mma_tf32(acc[mi][ni], af[mi], bf[ni][0], bf[ni][1]);
        }

        if (t + 1 < nt) {
            const int nxt = cur ^ 1;
            uint4 ua0 = {f2tf(a0.x), f2tf(a0.y), f2tf(a0.z), f2tf(a0.w)};
            uint4 ua1 = {f2tf(a1.x), f2tf(a1.y), f2tf(a1.z), f2tf(a1.w)};
            uint4 uw0 = {f2tf(w0.x), f2tf(w0.y), f2tf(w0.z), f2tf(w0.w)};
            uint4 uw1 = {f2tf(w1.x), f2tf(w1.y), f2tf(w1.z), f2tf(w1.w)};
            *reinterpret_cast<uint4*>(&As[nxt][a_row][a_kq])     = ua0;
            *reinterpret_cast<uint4*>(&As[nxt][a_row][a_kq + 4]) = ua1;
            *reinterpret_cast<uint4*>(&Bs[nxt][b_row][b_col])      = uw0;
            *reinterpret_cast<uint4*>(&Bs[nxt][b_row][b_col + 64]) = uw1;
        }
        __syncthreads();
    }

    // Epilogue: C fragments (rows ..+g, ..+g+8; cols ..+2tg, +2tg+1) + bias
    #pragma unroll
    for (int ni = 0; ni < 4; ni++) {
        const int col = n0 + wn * 32 + 8 * ni + 2 * tg;
        const float2 bv = *reinterpret_cast<const float2*>(&bias[col]);
        #pragma unroll
        for (int mi = 0; mi < 4; mi++) {
            const int r0 = m0 + wm * 64 + 16 * mi + g;
            float2 o0 = {acc[mi][ni][0] + bv.x, acc[mi][ni][1] + bv.y};
            float2 o1 = {acc[mi][ni][2] + bv.x, acc[mi][ni][3] + bv.y};
            *reinterpret_cast<float2*>(&C[(size_t)r0 * N + col])       = o0;
            *reinterpret_cast<float2*>(&C[(size_t)(r0 + 8) * N + col]) = o1;
        }
    }
}

// ---------------------------------------------------------------------------
// Causal GQA flash attention via tf32 mma.
// grid (S/64, H, B), 128 threads = 4 warps; warp w owns query rows 16w..16w+15.
// Q fragments register-resident (x 1/sqrt(dk)); K smem [key][dk] stride 68;
// V smem transposed [dk][key] stride 68 with the keys of every 8-group
// PERMUTED by sigma(s) = (s>>1)|((s&1)<<2). This makes the S C-fragment
// layout directly reusable as the P A-fragment for the PV mma (a = {c0,c2,
// c1,c3}) with no shuffles. Softmax/masking are key-order invariant.
// NOTE: no min-blocks clause — capping regs at 128 caused spills (R7).
// ---------------------------------------------------------------------------
__global__ __launch_bounds__(128)
void attn_mma(const float* __restrict__ qh, const float* __restrict__ kh,
              const float* __restrict__ vh, float* __restrict__ out) {
    __shared__ __align__(16) unsigned Ks[64][68];   // [key][dk] (also Q staging)
    __shared__ __align__(16) unsigned Vt[64][68];   // [dk][key-permuted]

    const int tid  = threadIdx.x;
    const int w    = tid >> 5;
    const int lane = tid & 31;
    const int g    = lane >> 2;
    const int tg   = lane & 3;
    const int bx   = blockIdx.x;
    const int h    = blockIdx.y;
    const int b    = blockIdx.z;
    const int kvh  = h >> 2;
    const int q0   = bx * 64;

    // Stage Q tile (rows q0..q0+63) into Ks, scaled, tf32
    if (tid < 64) {
        const float* qp = qh + ((size_t)(b * cS + q0 + tid)) * cD + h * cDK;
        #pragma unroll
        for (int i = 0; i < 16; i++) {
            float4 v = reinterpret_cast<const float4*>(qp)[i];
            uint4 u = {f2tf(v.x * 0.125f), f2tf(v.y * 0.125f),
                       f2tf(v.z * 0.125f), f2tf(v.w * 0.125f)};
            *reinterpret_cast<uint4*>(&Ks[tid][4 * i]) = u;
        }
    }
    __syncthreads();

    // Q A-fragments: 8 k-steps; rows 16w+g(+8), cols 8ks+tg(+4)
    unsigned qf[8][4];
    #pragma unroll
    for (int ks = 0; ks < 8; ks++) {
        qf[ks][0] = Ks[16 * w + g][8 * ks + tg];
        qf[ks][1] = Ks[16 * w + g + 8][8 * ks + tg];
        qf[ks][2] = Ks[16 * w + g][8 * ks + tg + 4];
        qf[ks][3] = Ks[16 * w + g + 8][8 * ks + tg + 4];
    }

    float O[8][4];
    #pragma unroll
    for (int ni = 0; ni < 8; ni++)
        #pragma unroll
        for (int f = 0; f < 4; f++) O[ni][f] = 0.f;
    float mr0 = -1e30f, mr1 = -1e30f;   // row maxima (rows g, g+8)
    float lr0 = 0.f, lr1 = 0.f;         // row sums

    for (int kt = 0; kt <= bx; kt++) {
        __syncthreads();   // previous tile compute done (also guards Q frag reads)
        // Load K/V tile: threads 0..63 -> V row (transposed + key-permuted),
        //                threads 64..127 -> K row (natural order).
        if (tid < 64) {
            const float* vp = vh + ((size_t)(b * cS + kt * 64 + tid)) * cNKV + kvh * cDK;
            // permuted column for this key within its 8-group
            const int scol = (tid & 56) | ((tid & 7) >> 1) | ((tid & 1) << 2);
            #pragma unroll
            for (int i = 0; i < 16; i++) {
                float4 v = reinterpret_cast<const float4*>(vp)[i];
                Vt[4 * i + 0][scol] = f2tf(v.x);
                Vt[4 * i + 1][scol] = f2tf(v.y);
                Vt[4 * i + 2][scol] = f2tf(v.z);
                Vt[4 * i + 3][scol] = f2tf(v.w);
            }
        } else {
            const int r = tid - 64;
            const float* kp = kh + ((size_t)(b * cS + kt * 64 + r)) * cNKV + kvh * cDK;
            #pragma unroll
            for (int i = 0; i < 16; i++) {
                float4 v = reinterpret_cast<const float4*>(kp)[i];
                uint4 u = {f2tf(v.x), f2tf(v.y), f2tf(v.z), f2tf(v.w)};
                *reinterpret_cast<uint4*>(&Ks[r][4 * i]) = u;
            }
        }
        __syncthreads();

        // S = Q @ K^T : 8 n-tiles of 8 keys
        float S[8][4];
        #pragma unroll
        for (int ni = 0; ni < 8; ni++) {
            S[ni][0] = S[ni][1] = S[ni][2] = S[ni][3] = 0.f;
            #pragma unroll
            for (int ks = 0; ks < 8; ks++) {
                unsigned b0 = Ks[8 * ni + g][8 * ks + tg];
                unsigned b1 = Ks[8 * ni + g][8 * ks + tg + 4];
                mma_tf32(S[ni], qf[ks], b0, b1);
            }
        }

        // Causal mask on diagonal tile (q0 == kt*64: compare in-tile indices)
        if (kt == bx) {
            const int r0 = 16 * w + g, r1 = r0 + 8;
            #pragma unroll
            for (int ni = 0; ni < 8; ni++) {
                const int c0 = 8 * ni + 2 * tg, c1 = c0 + 1;
                if (c0 > r0) S[ni][0] = -1e30f;
                if (c1 > r0) S[ni][1] = -1e30f;
                if (c0 > r1) S[ni][2] = -1e30f;
                if (c1 > r1) S[ni][3] = -1e30f;
            }
        }

        // Online softmax (rows g and g+8 per thread; quad butterfly)
        float mx0 = -1e30f, mx1 = -1e30f;
        #pragma unroll
        for (int ni = 0; ni < 8; ni++) {
            mx0 = fmaxf(mx0, fmaxf(S[ni][0], S[ni][1]));
            mx1 = fmaxf(mx1, fmaxf(S[ni][2], S[ni][3]));
        }
        mx0 = fmaxf(mx0, __shfl_xor_sync(0xffffffffu, mx0, 1));
        mx0 = fmaxf(mx0, __shfl_xor_sync(0xffffffffu, mx0, 2));
        mx1 = fmaxf(mx1, __shfl_xor_sync(0xffffffffu, mx1, 1));
        mx1 = fmaxf(mx1, __shfl_xor_sync(0xffffffffu, mx1, 2));

        const float mn0 = fmaxf(mr0, mx0), mn1 = fmaxf(mr1, mx1);
        const float c0 = __expf(mr0 - mn0), c1 = __expf(mr1 - mn1);
        mr0 = mn0; mr1 = mn1;

        float s0 = 0.f, s1 = 0.f;
        #pragma unroll
        for (int ni = 0; ni < 8; ni++) {
            float p0 = __expf(S[ni][0] - mn0);
            float p1 = __expf(S[ni][1] - mn0);
            float p2 = __expf(S[ni][2] - mn1);
            float p3 = __expf(S[ni][3] - mn1);
            s0 += p0 + p1;
            s1 += p2 + p3;
            // store tf32 bits of P in place
            S[ni][0] = __uint_as_float(f2tf(p0));
            S[ni][1] = __uint_as_float(f2tf(p1));
            S[ni][2] = __uint_as_float(f2tf(p2));
            S[ni][3] = __uint_as_float(f2tf(p3));
        }
        s0 += __shfl_xor_sync(0xffffffffu, s0, 1);
        s0 += __shfl_xor_sync(0xffffffffu, s0, 2);
        s1 += __shfl_xor_sync(0xffffffffu, s1, 1);
        s1 += __shfl_xor_sync(0xffffffffu, s1, 2);
        lr0 = lr0 * c0 + s0;
        lr1 = lr1 * c1 + s1;
        #pragma unroll
        for (int ni = 0; ni < 8; ni++) {
            O[ni][0] *= c0; O[ni][1] *= c0;
            O[ni][2] *= c1; O[ni][3] *= c1;
        }

        // O += P @ V : C-fragment of S reused directly as A-fragment
        // (keys permuted in Vt so no shuffle needed): a = {c0, c2, c1, c3}.
        #pragma unroll
        for (int ks = 0; ks < 8; ks++) {
            unsigned a[4];
            a[0] = __float_as_uint(S[ks][0]);
            a[1] = __float_as_uint(S[ks][2]);
            a[2] = __float_as_uint(S[ks][1]);
            a[3] = __float_as_uint(S[ks][3]);
            #pragma unroll
            for (int ni = 0; ni < 8; ni++) {
                unsigned b0 = Vt[8 * ni + g][8 * ks + tg];
                unsigned b1 = Vt[8 * ni + g][8 * ks + tg + 4];
                mma_tf32(O[ni], a, b0, b1);
            }
        }
    }

    // Normalize + store
    const float inv0 = 1.f / lr0, inv1 = 1.f / lr1;
    const int r0 = q0 + 16 * w + g;
    float* op0 = out + ((size_t)(b * cS + r0)) * cD + h * cDK;
    float* op1 = op0 + (size_t)8 * cD;
    #pragma unroll
    for (int ni = 0; ni < 8; ni++) {
        float2 o0 = {O[ni][0] * inv0, O[ni][1] * inv0};
        float2 o1 = {O[ni][2] * inv1, O[ni][3] * inv1};
        *reinterpret_cast<float2*>(op0 + 8 * ni + 2 * tg) = o0;
        *reinterpret_cast<float2*>(op1 + 8 * ni + 2 * tg) = o1;
    }
}

// ---------------------------------------------------------------------------
// Launch
// ---------------------------------------------------------------------------
extern "C" void kernel_launch(void* const* d_in, const int* in_sizes, int n_in,
                              void* d_out, int out_size) {
    const float* q  = (const float*)d_in[0];
    const float* k  = (const float*)d_in[1];
    const float* v  = (const float*)d_in[2];
    const float* Wq = (const float*)d_in[4];
    const float* bq = (const float*)d_in[5];
    const float* Wk = (const float*)d_in[6];
    const float* bk = (const float*)d_in[7];
    const float* Wv = (const float*)d_in[8];
    const float* bv = (const float*)d_in[9];
    const float* Wo = (const float*)d_in[10];
    const float* bo = (const float*)d_in[11];
    float* out = (float*)d_out;

    float *qh, *kh, *vh, *att;
    cudaGetSymbolAddress((void**)&qh,  g_qh);
    cudaGetSymbolAddress((void**)&kh,  g_kh);
    cudaGetSymbolAddress((void**)&vh,  g_vh);
    cudaGetSymbolAddress((void**)&att, g_att);

    gemm_mma<<<dim3(cD   / 128, cM / 128), 256>>>(q, Wq, bq, qh, cM, cD,   cD);
    gemm_mma<<<dim3(cNKV / 128, cM / 128), 256>>>(k, Wk, bk, kh, cM, cNKV, cD);
    gemm_mma<<<dim3(cNKV / 128, cM / 128), 256>>>(v, Wv, bv, vh, cM, cNKV, cD);

    attn_mma<<<dim3(cS / 64, cH, cB), 128>>>(qh, kh, vh, att);

    gemm_mma<<<dim3(cD / 128, cM / 128), 256>>>(att, Wo, bo, out, cM, cD, cD);
}

// round 14
// speedup vs baseline: 1.9085x; 1.2575x over previous
#include <cuda_runtime.h>
#include <math.h>
#include <stdint.h>

// Problem constants
constexpr int cB   = 2;
constexpr int cS   = 2048;
constexpr int cD   = 1024;
constexpr int cH   = 16;
constexpr int cHKV = 4;
constexpr int cDK  = 64;
constexpr int cNKV = cHKV * cDK;   // 256
constexpr int cM   = cB * cS;      // 4096

// Scratch (no allocations allowed)
__device__ float g_qh [cB * cS * cD];
__device__ float g_kh [cB * cS * cNKV];
__device__ float g_vh [cB * cS * cNKV];
__device__ float g_att[cB * cS * cD];

// ---------------------------------------------------------------------------
// tf32 / cp.async helpers
// ---------------------------------------------------------------------------
__device__ __forceinline__ unsigned f2tf(float f) {
    unsigned u;
    asm("cvt.rna.tf32.f32 %0, %1;" : "=r"(u) : "f"(f));
    return u;
}

__device__ __forceinline__ void mma_tf32(float d[4], const unsigned a[4],
                                         unsigned b0, unsigned b1) {
    asm("mma.sync.aligned.m16n8k8.row.col.f32.tf32.tf32.f32 "
        "{%0,%1,%2,%3}, {%4,%5,%6,%7}, {%8,%9}, {%0,%1,%2,%3};"
        : "+f"(d[0]), "+f"(d[1]), "+f"(d[2]), "+f"(d[3])
        : "r"(a[0]), "r"(a[1]), "r"(a[2]), "r"(a[3]), "r"(b0), "r"(b1));
}

__device__ __forceinline__ void cp_async16(unsigned dst_smem, const void* src) {
    asm volatile("cp.async.cg.shared.global [%0], [%1], 16;\n"
                 :: "r"(dst_smem), "l"(src));
}
#define CP_COMMIT() asm volatile("cp.async.commit_group;\n" ::)
#define CP_WAIT0()  asm volatile("cp.async.wait_group 0;\n" ::: "memory")

// ---------------------------------------------------------------------------
// GEMM + bias via tf32 mma: C[M,N] = (A[M,K] @ W[K,N] + bias[N]) * oscale
// If rnd != 0, output is rounded to tf32 (bits stored in the float) — used for
// the Q/K/V projections so the attention kernel can consume raw bits with no
// conversion. Q additionally folds the 1/sqrt(dk)=0.125 scale here (exact).
// 128x128 tile, BK=16, 256 threads = 8 warps, double-buffered smem.
// ---------------------------------------------------------------------------
__global__ __launch_bounds__(256)
void gemm_mma(const float* __restrict__ A, const float* __restrict__ W,
              const float* __restrict__ bias, float* __restrict__ C,
              int M, int N, int K, float oscale, int rnd) {
    __shared__ __align__(16) unsigned As[2][128][20];   // [m][k], stride 20
    __shared__ __align__(16) unsigned Bs[2][16][136];   // [k][n], stride 136

    const int tid  = threadIdx.x;
    const int w    = tid >> 5;
    const int lane = tid & 31;
    const int g    = lane >> 2;
    const int tg   = lane & 3;
    const int wm   = w & 1;
    const int wn   = w >> 1;
    const int m0   = blockIdx.y * 128;
    const int n0   = blockIdx.x * 128;

    const int a_row = tid >> 1;
    const int a_kq  = (tid & 1) * 8;
    const int b_row = tid >> 4;
    const int b_col = (tid & 15) * 4;

    const float* Ap  = A + (size_t)(m0 + a_row) * K + a_kq;
    const float* Bp0 = W + (size_t)b_row * N + n0 + b_col;
    const float* Bp1 = Bp0 + 64;

    float acc[4][4][4];
    #pragma unroll
    for (int mi = 0; mi < 4; mi++)
        #pragma unroll
        for (int ni = 0; ni < 4; ni++)
            #pragma unroll
            for (int f = 0; f < 4; f++) acc[mi][ni][f] = 0.f;

    const int nt = K / 16;

    {
        float4 a0 = *reinterpret_cast<const float4*>(Ap);
        float4 a1 = *reinterpret_cast<const float4*>(Ap + 4);
        float4 w0 = *reinterpret_cast<const float4*>(Bp0);
        float4 w1 = *reinterpret_cast<const float4*>(Bp1);
        uint4 ua0 = {f2tf(a0.x), f2tf(a0.y), f2tf(a0.z), f2tf(a0.w)};
        uint4 ua1 = {f2tf(a1.x), f2tf(a1.y), f2tf(a1.z), f2tf(a1.w)};
        uint4 uw0 = {f2tf(w0.x), f2tf(w0.y), f2tf(w0.z), f2tf(w0.w)};
        uint4 uw1 = {f2tf(w1.x), f2tf(w1.y), f2tf(w1.z), f2tf(w1.w)};
        *reinterpret_cast<uint4*>(&As[0][a_row][a_kq])     = ua0;
        *reinterpret_cast<uint4*>(&As[0][a_row][a_kq + 4]) = ua1;
        *reinterpret_cast<uint4*>(&Bs[0][b_row][b_col])      = uw0;
        *reinterpret_cast<uint4*>(&Bs[0][b_row][b_col + 64]) = uw1;
    }
    __syncthreads();

    for (int t = 0; t < nt; t++) {
        const int cur = t & 1;
        float4 a0, a1, w0, w1;
        if (t + 1 < nt) {
            const size_t ko = (size_t)(t + 1) * 16;
            a0 = *reinterpret_cast<const float4*>(Ap + ko);
            a1 = *reinterpret_cast<const float4*>(Ap + ko + 4);
            w0 = *reinterpret_cast<const float4*>(Bp0 + ko * N);
            w1 = *reinterpret_cast<const float4*>(Bp1 + ko * N);
        }

        #pragma unroll
        for (int kk = 0; kk < 2; kk++) {
            unsigned af[4][4];
            #pragma unroll
            for (int mi = 0; mi < 4; mi++) {
                const int r = wm * 64 + 16 * mi + g;
                af[mi][0] = As[cur][r][8 * kk + tg];
                af[mi][1] = As[cur][r + 8][8 * kk + tg];
                af[mi][2] = As[cur][r][8 * kk + tg + 4];
                af[mi][3] = As[cur][r + 8][8 * kk + tg + 4];
            }
            unsigned bf[4][2];
            #pragma unroll
            for (int ni = 0; ni < 4; ni++) {
                const int c = wn * 32 + 8 * ni + g;
                bf[ni][0] = Bs[cur][8 * kk + tg][c];
                bf[ni][1] = Bs[cur][8 * kk + tg + 4][c];
            }
            #pragma unroll
            for (int mi = 0; mi < 4; mi++)
                #pragma unroll
                for (int ni = 0; ni < 4; ni++)
                    mma_tf32(acc[mi][ni], af[mi], bf[ni][0], bf[ni][1]);
        }

        if (t + 1 < nt) {
            const int nxt = cur ^ 1;
            uint4 ua0 = {f2tf(a0.x), f2tf(a0.y), f2tf(a0.z), f2tf(a0.w)};
            uint4 ua1 = {f2tf(a1.x), f2tf(a1.y), f2tf(a1.z), f2tf(a1.w)};
            uint4 uw0 = {f2tf(w0.x), f2tf(w0.y), f2tf(w0.z), f2tf(w0.w)};
            uint4 uw1 = {f2tf(w1.x), f2tf(w1.y), f2tf(w1.z), f2tf(w1.w)};
            *reinterpret_cast<uint4*>(&As[nxt][a_row][a_kq])     = ua0;
            *reinterpret_cast<uint4*>(&As[nxt][a_row][a_kq + 4]) = ua1;
            *reinterpret_cast<uint4*>(&Bs[nxt][b_row][b_col])      = uw0;
            *reinterpret_cast<uint4*>(&Bs[nxt][b_row][b_col + 64]) = uw1;
        }
        __syncthreads();
    }

    #pragma unroll
    for (int ni = 0; ni < 4; ni++) {
        const int col = n0 + wn * 32 + 8 * ni + 2 * tg;
        const float2 bv = *reinterpret_cast<const float2*>(&bias[col]);
        #pragma unroll
        for (int mi = 0; mi < 4; mi++) {
            const int r0 = m0 + wm * 64 + 16 * mi + g;
            float v00 = acc[mi][ni][0] + bv.x;
            float v01 = acc[mi][ni][1] + bv.y;
            float v10 = acc[mi][ni][2] + bv.x;
            float v11 = acc[mi][ni][3] + bv.y;
            if (rnd) {
                v00 = __uint_as_float(f2tf(v00 * oscale));
                v01 = __uint_as_float(f2tf(v01 * oscale));
                v10 = __uint_as_float(f2tf(v10 * oscale));
                v11 = __uint_as_float(f2tf(v11 * oscale));
            }
            float2 o0 = {v00, v01};
            float2 o1 = {v10, v11};
            *reinterpret_cast<float2*>(&C[(size_t)r0 * N + col])       = o0;
            *reinterpret_cast<float2*>(&C[(size_t)(r0 + 8) * N + col]) = o1;
        }
    }
}

// ---------------------------------------------------------------------------
// Causal GQA flash attention, tf32 mma, cp.async double-buffered K/V.
// grid (S/64, H, B), 128 threads = 4 warps. Inputs qh/kh/vh hold tf32-rounded
// bits (qh pre-scaled by 1/8) so all staging is pure byte copies.
// Dynamic smem layout (words): Ks[2][64][68] | Vt[64][68] | Vr[64][68].
// Pipeline per tile: transpose Vr->Vt (thr 0-63, sigma-permuted) while
// thr 64-127 cp.async K(t+1)->Ks[nxt]; sync; cp.async V(t+1)->Vr (all);
// compute S/softmax/PV; wait; sync.
// ---------------------------------------------------------------------------
constexpr int ATTN_SMEM_WORDS = 2 * 64 * 68 + 64 * 68 + 64 * 68;   // 17408
constexpr int ATTN_SMEM_BYTES = ATTN_SMEM_WORDS * 4;               // 69632

__global__ __launch_bounds__(128)
void attn_mma(const float* __restrict__ qh, const float* __restrict__ kh,
              const float* __restrict__ vh, float* __restrict__ out) {
    extern __shared__ unsigned dsm[];
    unsigned* Ks = dsm;                       // [2][64][68]
    unsigned* Vt = dsm + 2 * 64 * 68;         // [64][68]  (also Q staging)
    unsigned* Vr = dsm + 3 * 64 * 68;         // [64][68]  raw V

    const int tid  = threadIdx.x;
    const int w    = tid >> 5;
    const int lane = tid & 31;
    const int g    = lane >> 2;
    const int tg   = lane & 3;
    const int bx   = blockIdx.x;
    const int h    = blockIdx.y;
    const int b    = blockIdx.z;
    const int kvh  = h >> 2;
    const int q0   = bx * 64;

    const float* kbase = kh + (size_t)b * cS * cNKV + kvh * cDK;
    const float* vbase = vh + (size_t)b * cS * cNKV + kvh * cDK;

    const unsigned ks_base = (unsigned)__cvta_generic_to_shared(Ks);
    const unsigned vr_base = (unsigned)__cvta_generic_to_shared(Vr);

    // Prologue: start K(0)/V(0) cp.async, stage Q into Vt meanwhile.
    #pragma unroll
    for (int j = 0; j < 8; j++) {
        const int c = tid + 128 * j;
        const int r = c >> 4, q = c & 15;
        cp_async16(ks_base + (r * 68 + q * 4) * 4, kbase + (size_t)r * cNKV + q * 4);
        cp_async16(vr_base + (r * 68 + q * 4) * 4, vbase + (size_t)r * cNKV + q * 4);
    }
    CP_COMMIT();

    if (tid < 64) {
        const float* qp = qh + ((size_t)(b * cS + q0 + tid)) * cD + h * cDK;
        #pragma unroll
        for (int i = 0; i < 16; i++)
            *reinterpret_cast<uint4*>(&Vt[tid * 68 + 4 * i]) =
                reinterpret_cast<const uint4*>(qp)[i];
    }
    __syncthreads();

    // Q A-fragments (bits already tf32, pre-scaled by 1/8)
    unsigned qf[8][4];
    #pragma unroll
    for (int ks = 0; ks < 8; ks++) {
        qf[ks][0] = Vt[(16 * w + g) * 68 + 8 * ks + tg];
        qf[ks][1] = Vt[(16 * w + g + 8) * 68 + 8 * ks + tg];
        qf[ks][2] = Vt[(16 * w + g) * 68 + 8 * ks + tg + 4];
        qf[ks][3] = Vt[(16 * w + g + 8) * 68 + 8 * ks + tg + 4];
    }
    CP_WAIT0();
    __syncthreads();   // K(0) in Ks[0], V(0) in Vr; qf extracted (Vt free)

    float O[8][4];
    #pragma unroll
    for (int ni = 0; ni < 8; ni++)
        #pragma unroll
        for (int f = 0; f < 4; f++) O[ni][f] = 0.f;
    float mr0 = -1e30f, mr1 = -1e30f;
    float lr0 = 0.f, lr1 = 0.f;

    for (int kt = 0; kt <= bx; kt++) {
        const int cur = kt & 1;
        const int nxt = cur ^ 1;

        // Phase 1: transpose V (thr 0-63) || prefetch K(t+1) (thr 64-127)
        if (tid < 64) {
            const int scol = (tid & 56) | ((tid & 7) >> 1) | ((tid & 1) << 2);
            #pragma unroll
            for (int i = 0; i < 16; i++) {
                uint4 v = *reinterpret_cast<const uint4*>(&Vr[tid * 68 + 4 * i]);
                Vt[(4 * i + 0) * 68 + scol] = v.x;
                Vt[(4 * i + 1) * 68 + scol] = v.y;
                Vt[(4 * i + 2) * 68 + scol] = v.z;
                Vt[(4 * i + 3) * 68 + scol] = v.w;
            }
        } else if (kt < bx) {
            const int t2 = tid - 64;
            #pragma unroll
            for (int j = 0; j < 16; j++) {
                const int c = t2 + 64 * j;
                const int r = c >> 4, q = c & 15;
                cp_async16(ks_base + (nxt * 64 * 68 + r * 68 + q * 4) * 4,
                           kbase + (size_t)((kt + 1) * 64 + r) * cNKV + q * 4);
            }
        }
        __syncthreads();   // Vt ready, Vr free

        // Phase 2: prefetch V(t+1) into Vr (all threads)
        if (kt < bx) {
            #pragma unroll
            for (int j = 0; j < 8; j++) {
                const int c = tid + 128 * j;
                const int r = c >> 4, q = c & 15;
                cp_async16(vr_base + (r * 68 + q * 4) * 4,
                           vbase + (size_t)((kt + 1) * 64 + r) * cNKV + q * 4);
            }
        }
        CP_COMMIT();

        // S = Q @ K^T
        float S[8][4];
        #pragma unroll
        for (int ni = 0; ni < 8; ni++) {
            S[ni][0] = S[ni][1] = S[ni][2] = S[ni][3] = 0.f;
            #pragma unroll
            for (int ks = 0; ks < 8; ks++) {
                unsigned b0 = Ks[cur * 64 * 68 + (8 * ni + g) * 68 + 8 * ks + tg];
                unsigned b1 = Ks[cur * 64 * 68 + (8 * ni + g) * 68 + 8 * ks + tg + 4];
                mma_tf32(S[ni], qf[ks], b0, b1);
            }
        }

        // Causal mask on diagonal tile
        if (kt == bx) {
            const int r0 = 16 * w + g, r1 = r0 + 8;
            #pragma unroll
            for (int ni = 0; ni < 8; ni++) {
                const int c0 = 8 * ni + 2 * tg, c1 = c0 + 1;
                if (c0 > r0) S[ni][0] = -1e30f;
                if (c1 > r0) S[ni][1] = -1e30f;
                if (c0 > r1) S[ni][2] = -1e30f;
                if (c1 > r1) S[ni][3] = -1e30f;
            }
        }

        // Online softmax
        float mx0 = -1e30f, mx1 = -1e30f;
        #pragma unroll
        for (int ni = 0; ni < 8; ni++) {
            mx0 = fmaxf(mx0, fmaxf(S[ni][0], S[ni][1]));
            mx1 = fmaxf(mx1, fmaxf(S[ni][2], S[ni][3]));
        }
        mx0 = fmaxf(mx0, __shfl_xor_sync(0xffffffffu, mx0, 1));
        mx0 = fmaxf(mx0, __shfl_xor_sync(0xffffffffu, mx0, 2));
        mx1 = fmaxf(mx1, __shfl_xor_sync(0xffffffffu, mx1, 1));
        mx1 = fmaxf(mx1, __shfl_xor_sync(0xffffffffu, mx1, 2));

        const float mn0 = fmaxf(mr0, mx0), mn1 = fmaxf(mr1, mx1);
        const float c0 = __expf(mr0 - mn0), c1 = __expf(mr1 - mn1);
        mr0 = mn0; mr1 = mn1;

        float s0 = 0.f, s1 = 0.f;
        #pragma unroll
        for (int ni = 0; ni < 8; ni++) {
            float p0 = __expf(S[ni][0] - mn0);
            float p1 = __expf(S[ni][1] - mn0);
            float p2 = __expf(S[ni][2] - mn1);
            float p3 = __expf(S[ni][3] - mn1);
            s0 += p0 + p1;
            s1 += p2 + p3;
            S[ni][0] = __uint_as_float(f2tf(p0));
            S[ni][1] = __uint_as_float(f2tf(p1));
            S[ni][2] = __uint_as_float(f2tf(p2));
            S[ni][3] = __uint_as_float(f2tf(p3));
        }
        s0 += __shfl_xor_sync(0xffffffffu, s0, 1);
        s0 += __shfl_xor_sync(0xffffffffu, s0, 2);
        s1 += __shfl_xor_sync(0xffffffffu, s1, 1);
        s1 += __shfl_xor_sync(0xffffffffu, s1, 2);
        lr0 = lr0 * c0 + s0;
        lr1 = lr1 * c1 + s1;
        #pragma unroll
        for (int ni = 0; ni < 8; ni++) {
            O[ni][0] *= c0; O[ni][1] *= c0;
            O[ni][2] *= c1; O[ni][3] *= c1;
        }

        // O += P @ V (sigma-permuted Vt: C-frag reused as A-frag, no shuffles)
        #pragma unroll
        for (int ks = 0; ks < 8; ks++) {
            unsigned a[4];
            a[0] = __float_as_uint(S[ks][0]);
            a[1] = __float_as_uint(S[ks][2]);
            a[2] = __float_as_uint(S[ks][1]);
            a[3] = __float_as_uint(S[ks][3]);
            #pragma unroll
            for (int ni = 0; ni < 8; ni++) {
                unsigned b0 = Vt[(8 * ni + g) * 68 + 8 * ks + tg];
                unsigned b1 = Vt[(8 * ni + g) * 68 + 8 * ks + tg + 4];
                mma_tf32(O[ni], a, b0, b1);
            }
        }

        CP_WAIT0();        // K(t+1), V(t+1) landed (overlapped with compute)
        __syncthreads();
    }

    // Normalize + store
    const float inv0 = 1.f / lr0, inv1 = 1.f / lr1;
    const int r0 = q0 + 16 * w + g;
    float* op0 = out + ((size_t)(b * cS + r0)) * cD + h * cDK;
    float* op1 = op0 + (size_t)8 * cD;
    #pragma unroll
    for (int ni = 0; ni < 8; ni++) {
        float2 o0 = {O[ni][0] * inv0, O[ni][1] * inv0};
        float2 o1 = {O[ni][2] * inv1, O[ni][3] * inv1};
        *reinterpret_cast<float2*>(op0 + 8 * ni + 2 * tg) = o0;
        *reinterpret_cast<float2*>(op1 + 8 * ni + 2 * tg) = o1;
    }
}

// ---------------------------------------------------------------------------
// Launch
// ---------------------------------------------------------------------------
extern "C" void kernel_launch(void* const* d_in, const int* in_sizes, int n_in,
                              void* d_out, int out_size) {
    const float* q  = (const float*)d_in[0];
    const float* k  = (const float*)d_in[1];
    const float* v  = (const float*)d_in[2];
    const float* Wq = (const float*)d_in[4];
    const float* bq = (const float*)d_in[5];
    const float* Wk = (const float*)d_in[6];
    const float* bk = (const float*)d_in[7];
    const float* Wv = (const float*)d_in[8];
    const float* bv = (const float*)d_in[9];
    const float* Wo = (const float*)d_in[10];
    const float* bo = (const float*)d_in[11];
    float* out = (float*)d_out;

    float *qh, *kh, *vh, *att;
    cudaGetSymbolAddress((void**)&qh,  g_qh);
    cudaGetSymbolAddress((void**)&kh,  g_kh);
    cudaGetSymbolAddress((void**)&vh,  g_vh);
    cudaGetSymbolAddress((void**)&att, g_att);

    cudaFuncSetAttribute(attn_mma, cudaFuncAttributeMaxDynamicSharedMemorySize,
                         ATTN_SMEM_BYTES);

    // Projections: tf32-rounded outputs; Q pre-scaled by 1/sqrt(dk)=0.125
    gemm_mma<<<dim3(cD   / 128, cM / 128), 256>>>(q, Wq, bq, qh, cM, cD,   cD, 0.125f, 1);
    gemm_mma<<<dim3(cNKV / 128, cM / 128), 256>>>(k, Wk, bk, kh, cM, cNKV, cD, 1.0f,   1);
    gemm_mma<<<dim3(cNKV / 128, cM / 128), 256>>>(v, Wv, bv, vh, cM, cNKV, cD, 1.0f,   1);

    attn_mma<<<dim3(cS / 64, cH, cB), 128, ATTN_SMEM_BYTES>>>(qh, kh, vh, att);

    // Output projection: plain fp32
    gemm_mma<<<dim3(cD / 128, cM / 128), 256>>>(att, Wo, bo, out, cM, cD, cD, 1.0f, 0);
}

// round 15
// speedup vs baseline: 1.9091x; 1.0003x over previous
#include <cuda_runtime.h>
#include <math.h>
#include <stdint.h>

// Problem constants
constexpr int cB   = 2;
constexpr int cS   = 2048;
constexpr int cD   = 1024;
constexpr int cH   = 16;
constexpr int cHKV = 4;
constexpr int cDK  = 64;
constexpr int cNKV = cHKV * cDK;   // 256
constexpr int cM   = cB * cS;      // 4096

// Scratch (no allocations allowed)
__device__ float    g_qh [cB * cS * cD];      // tf32 bits (Q/8)
__device__ float    g_kh [cB * cS * cNKV];    // tf32 bits
__device__ float    g_vh [cB * cS * cNKV];    // tf32 bits
__device__ float    g_att[cB * cS * cD];      // tf32 bits (attention out)
// pre-rounded tf32-bit copies of inputs/weights
__device__ unsigned g_qr [cM * cD];
__device__ unsigned g_kr [cM * cD];
__device__ unsigned g_vr [cM * cD];
__device__ unsigned g_wq [cD * cD];
__device__ unsigned g_wk [cD * cNKV];
__device__ unsigned g_wv [cD * cNKV];
__device__ unsigned g_wo [cD * cD];

// ---------------------------------------------------------------------------
// tf32 / cp.async helpers
// ---------------------------------------------------------------------------
__device__ __forceinline__ unsigned f2tf(float f) {
    unsigned u;
    asm("cvt.rna.tf32.f32 %0, %1;" : "=r"(u) : "f"(f));
    return u;
}

__device__ __forceinline__ void mma_tf32(float d[4], const unsigned a[4],
                                         unsigned b0, unsigned b1) {
    asm("mma.sync.aligned.m16n8k8.row.col.f32.tf32.tf32.f32 "
        "{%0,%1,%2,%3}, {%4,%5,%6,%7}, {%8,%9}, {%0,%1,%2,%3};"
        : "+f"(d[0]), "+f"(d[1]), "+f"(d[2]), "+f"(d[3])
        : "r"(a[0]), "r"(a[1]), "r"(a[2]), "r"(a[3]), "r"(b0), "r"(b1));
}

__device__ __forceinline__ void cp_async16(unsigned dst_smem, const void* src) {
    asm volatile("cp.async.cg.shared.global [%0], [%1], 16;\n"
                 :: "r"(dst_smem), "l"(src));
}
#define CP_COMMIT() asm volatile("cp.async.commit_group;\n" ::)
#define CP_WAIT0()  asm volatile("cp.async.wait_group 0;\n" ::: "memory")

// ---------------------------------------------------------------------------
// Elementwise rna tf32 pre-round: dst[i] = tf32(src[i]); vectorized x4.
// ---------------------------------------------------------------------------
__global__ __launch_bounds__(256)
void rnd_tf32_kernel(const float4* __restrict__ src, uint4* __restrict__ dst,
                     int n4) {
    int i = blockIdx.x * 256 + threadIdx.x;
    if (i < n4) {
        float4 v = src[i];
        uint4 u = {f2tf(v.x), f2tf(v.y), f2tf(v.z), f2tf(v.w)};
        dst[i] = u;
    }
}

// ---------------------------------------------------------------------------
// GEMM + bias, tf32 mma, cp.async pipeline. A and W hold PRE-ROUNDED tf32
// bits — no cvt anywhere in the kernel, no load-register staging.
// C[M,N] = (A@W + bias) * oscale, optionally tf32-rounded output (rnd).
// 128x128 tile, BK=16, 256 threads = 8 warps (2m x 4n), double-buffered smem.
// ---------------------------------------------------------------------------
__global__ __launch_bounds__(256)
void gemm_mma_async(const unsigned* __restrict__ A, const unsigned* __restrict__ W,
                    const float* __restrict__ bias, float* __restrict__ C,
                    int M, int N, int K, float oscale, int rnd) {
    __shared__ __align__(16) unsigned As[2][128][20];   // [m][k], stride 20
    __shared__ __align__(16) unsigned Bs[2][16][136];   // [k][n], stride 136

    const int tid  = threadIdx.x;
    const int w    = tid >> 5;
    const int lane = tid & 31;
    const int g    = lane >> 2;
    const int tg   = lane & 3;
    const int wm   = w & 1;
    const int wn   = w >> 1;
    const int m0   = blockIdx.y * 128;
    const int n0   = blockIdx.x * 128;

    const int a_row = tid >> 1;            // 0..127
    const int a_kq  = (tid & 1) * 8;       // 0 or 8
    const int b_row = tid >> 4;            // 0..15
    const int b_col = (tid & 15) * 4;      // 0..60

    const unsigned* Ap  = A + (size_t)(m0 + a_row) * K + a_kq;
    const unsigned* Bp0 = W + (size_t)b_row * N + n0 + b_col;
    const unsigned* Bp1 = Bp0 + 64;

    const unsigned as_base = (unsigned)__cvta_generic_to_shared(&As[0][0][0]);
    const unsigned bs_base = (unsigned)__cvta_generic_to_shared(&Bs[0][0][0]);
    const unsigned as_off  = (a_row * 20 + a_kq) * 4;
    const unsigned bs_off  = (b_row * 136 + b_col) * 4;
    const unsigned as_buf  = 128 * 20 * 4;
    const unsigned bs_buf  = 16 * 136 * 4;

    float acc[4][4][4];
    #pragma unroll
    for (int mi = 0; mi < 4; mi++)
        #pragma unroll
        for (int ni = 0; ni < 4; ni++)
            #pragma unroll
            for (int f = 0; f < 4; f++) acc[mi][ni][f] = 0.f;

    const int nt = K / 16;

    // Prologue: tile 0 -> buffer 0
    cp_async16(as_base + as_off,      Ap);
    cp_async16(as_base + as_off + 16, Ap + 4);
    cp_async16(bs_base + bs_off,       Bp0);
    cp_async16(bs_base + bs_off + 256, Bp1);   // +64 words = 256 B
    CP_COMMIT();
    CP_WAIT0();
    __syncthreads();

    for (int t = 0; t < nt; t++) {
        const int cur = t & 1;
        if (t + 1 < nt) {
            const int nxt = cur ^ 1;
            const size_t ko = (size_t)(t + 1) * 16;
            cp_async16(as_base + nxt * as_buf + as_off,      Ap + ko);
            cp_async16(as_base + nxt * as_buf + as_off + 16, Ap + ko + 4);
            cp_async16(bs_base + nxt * bs_buf + bs_off,       Bp0 + ko * N);
            cp_async16(bs_base + nxt * bs_buf + bs_off + 256, Bp1 + ko * N);
        }
        CP_COMMIT();

        #pragma unroll
        for (int kk = 0; kk < 2; kk++) {
            unsigned af[4][4];
            #pragma unroll
            for (int mi = 0; mi < 4; mi++) {
                const int r = wm * 64 + 16 * mi + g;
                af[mi][0] = As[cur][r][8 * kk + tg];
                af[mi][1] = As[cur][r + 8][8 * kk + tg];
                af[mi][2] = As[cur][r][8 * kk + tg + 4];
                af[mi][3] = As[cur][r + 8][8 * kk + tg + 4];
            }
            unsigned bf[4][2];
            #pragma unroll
            for (int ni = 0; ni < 4; ni++) {
                const int c = wn * 32 + 8 * ni + g;
                bf[ni][0] = Bs[cur][8 * kk + tg][c];
                bf[ni][1] = Bs[cur][8 * kk + tg + 4][c];
            }
            #pragma unroll
            for (int mi = 0; mi < 4; mi++)
                #pragma unroll
                for (int ni = 0; ni < 4; ni++)
                    mma_tf32(acc[mi][ni], af[mi], bf[ni][0], bf[ni][1]);
        }

        CP_WAIT0();
        __syncthreads();
    }

    // Epilogue: + bias, optional tf32 rounding of output
    #pragma unroll
    for (int ni = 0; ni < 4; ni++) {
        const int col = n0 + wn * 32 + 8 * ni + 2 * tg;
        const float2 bv = *reinterpret_cast<const float2*>(&bias[col]);
        #pragma unroll
        for (int mi = 0; mi < 4; mi++) {
            const int r0 = m0 + wm * 64 + 16 * mi + g;
            float v00 = acc[mi][ni][0] + bv.x;
            float v01 = acc[mi][ni][1] + bv.y;
            float v10 = acc[mi][ni][2] + bv.x;
            float v11 = acc[mi][ni][3] + bv.y;
            if (rnd) {
                v00 = __uint_as_float(f2tf(v00 * oscale));
                v01 = __uint_as_float(f2tf(v01 * oscale));
                v10 = __uint_as_float(f2tf(v10 * oscale));
                v11 = __uint_as_float(f2tf(v11 * oscale));
            }
            float2 o0 = {v00, v01};
            float2 o1 = {v10, v11};
            *reinterpret_cast<float2*>(&C[(size_t)r0 * N + col])       = o0;
            *reinterpret_cast<float2*>(&C[(size_t)(r0 + 8) * N + col]) = o1;
        }
    }
}

// ---------------------------------------------------------------------------
// Causal GQA flash attention, tf32 mma, cp.async double-buffered K/V.
// Identical to R14 except the epilogue stores tf32-rounded bits (the same
// rna cvt the O-projection previously applied at load time).
// ---------------------------------------------------------------------------
constexpr int ATTN_SMEM_WORDS = 2 * 64 * 68 + 64 * 68 + 64 * 68;   // 17408
constexpr int ATTN_SMEM_BYTES = ATTN_SMEM_WORDS * 4;               // 69632

__global__ __launch_bounds__(128)
void attn_mma(const float* __restrict__ qh, const float* __restrict__ kh,
              const float* __restrict__ vh, float* __restrict__ out) {
    extern __shared__ unsigned dsm[];
    unsigned* Ks = dsm;                       // [2][64][68]
    unsigned* Vt = dsm + 2 * 64 * 68;         // [64][68]  (also Q staging)
    unsigned* Vr = dsm + 3 * 64 * 68;         // [64][68]  raw V

    const int tid  = threadIdx.x;
    const int w    = tid >> 5;
    const int lane = tid & 31;
    const int g    = lane >> 2;
    const int tg   = lane & 3;
    const int bx   = blockIdx.x;
    const int h    = blockIdx.y;
    const int b    = blockIdx.z;
    const int kvh  = h >> 2;
    const int q0   = bx * 64;

    const float* kbase = kh + (size_t)b * cS * cNKV + kvh * cDK;
    const float* vbase = vh + (size_t)b * cS * cNKV + kvh * cDK;

    const unsigned ks_base = (unsigned)__cvta_generic_to_shared(Ks);
    const unsigned vr_base = (unsigned)__cvta_generic_to_shared(Vr);

    // Prologue: start K(0)/V(0) cp.async, stage Q into Vt meanwhile.
    #pragma unroll
    for (int j = 0; j < 8; j++) {
        const int c = tid + 128 * j;
        const int r = c >> 4, q = c & 15;
        cp_async16(ks_base + (r * 68 + q * 4) * 4, kbase + (size_t)r * cNKV + q * 4);
        cp_async16(vr_base + (r * 68 + q * 4) * 4, vbase + (size_t)r * cNKV + q * 4);
    }
    CP_COMMIT();

    if (tid < 64) {
        const float* qp = qh + ((size_t)(b * cS + q0 + tid)) * cD + h * cDK;
        #pragma unroll
        for (int i = 0; i < 16; i++)
            *reinterpret_cast<uint4*>(&Vt[tid * 68 + 4 * i]) =
                reinterpret_cast<const uint4*>(qp)[i];
    }
    __syncthreads();

    // Q A-fragments (bits already tf32, pre-scaled by 1/8)
    unsigned qf[8][4];
    #pragma unroll
    for (int ks = 0; ks < 8; ks++) {
        qf[ks][0] = Vt[(16 * w + g) * 68 + 8 * ks + tg];
        qf[ks][1] = Vt[(16 * w + g + 8) * 68 + 8 * ks + tg];
        qf[ks][2] = Vt[(16 * w + g) * 68 + 8 * ks + tg + 4];
        qf[ks][3] = Vt[(16 * w + g + 8) * 68 + 8 * ks + tg + 4];
    }
    CP_WAIT0();
    __syncthreads();   // K(0) in Ks[0], V(0) in Vr; qf extracted (Vt free)

    float O[8][4];
    #pragma unroll
    for (int ni = 0; ni < 8; ni++)
        #pragma unroll
        for (int f = 0; f < 4; f++) O[ni][f] = 0.f;
    float mr0 = -1e30f, mr1 = -1e30f;
    float lr0 = 0.f, lr1 = 0.f;

    for (int kt = 0; kt <= bx; kt++) {
        const int cur = kt & 1;
        const int nxt = cur ^ 1;

        // Phase 1: transpose V (thr 0-63) || prefetch K(t+1) (thr 64-127)
        if (tid < 64) {
            const int scol = (tid & 56) | ((tid & 7) >> 1) | ((tid & 1) << 2);
            #pragma unroll
            for (int i = 0; i < 16; i++) {
                uint4 v = *reinterpret_cast<const uint4*>(&Vr[tid * 68 + 4 * i]);
                Vt[(4 * i + 0) * 68 + scol] = v.x;
                Vt[(4 * i + 1) * 68 + scol] = v.y;
                Vt[(4 * i + 2) * 68 + scol] = v.z;
                Vt[(4 * i + 3) * 68 + scol] = v.w;
            }
        } else if (kt < bx) {
            const int t2 = tid - 64;
            #pragma unroll
            for (int j = 0; j < 16; j++) {
                const int c = t2 + 64 * j;
                const int r = c >> 4, q = c & 15;
                cp_async16(ks_base + (nxt * 64 * 68 + r * 68 + q * 4) * 4,
                           kbase + (size_t)((kt + 1) * 64 + r) * cNKV + q * 4);
            }
        }
        __syncthreads();   // Vt ready, Vr free

        // Phase 2: prefetch V(t+1) into Vr (all threads)
        if (kt < bx) {
            #pragma unroll
            for (int j = 0; j < 8; j++) {
                const int c = tid + 128 * j;
                const int r = c >> 4, q = c & 15;
                cp_async16(vr_base + (r * 68 + q * 4) * 4,
                           vbase + (size_t)((kt + 1) * 64 + r) * cNKV + q * 4);
            }
        }
        CP_COMMIT();

        // S = Q @ K^T
        float S[8][4];
        #pragma unroll
        for (int ni = 0; ni < 8; ni++) {
            S[ni][0] = S[ni][1] = S[ni][2] = S[ni][3] = 0.f;
            #pragma unroll
            for (int ks = 0; ks < 8; ks++) {
                unsigned b0 = Ks[cur * 64 * 68 + (8 * ni + g) * 68 + 8 * ks + tg];
                unsigned b1 = Ks[cur * 64 * 68 + (8 * ni + g) * 68 + 8 * ks + tg + 4];
                mma_tf32(S[ni], qf[ks], b0, b1);
            }
        }

        // Causal mask on diagonal tile
        if (kt == bx) {
            const int r0 = 16 * w + g, r1 = r0 + 8;
            #pragma unroll
            for (int ni = 0; ni < 8; ni++) {
                const int c0 = 8 * ni + 2 * tg, c1 = c0 + 1;
                if (c0 > r0) S[ni][0] = -1e30f;
                if (c1 > r0) S[ni][1] = -1e30f;
                if (c0 > r1) S[ni][2] = -1e30f;
                if (c1 > r1) S[ni][3] = -1e30f;
            }
        }

        // Online softmax
        float mx0 = -1e30f, mx1 = -1e30f;
        #pragma unroll
        for (int ni = 0; ni < 8; ni++) {
            mx0 = fmaxf(mx0, fmaxf(S[ni][0], S[ni][1]));
            mx1 = fmaxf(mx1, fmaxf(S[ni][2], S[ni][3]));
        }
        mx0 = fmaxf(mx0, __shfl_xor_sync(0xffffffffu, mx0, 1));
        mx0 = fmaxf(mx0, __shfl_xor_sync(0xffffffffu, mx0, 2));
        mx1 = fmaxf(mx1, __shfl_xor_sync(0xffffffffu, mx1, 1));
        mx1 = fmaxf(mx1, __shfl_xor_sync(0xffffffffu, mx1, 2));

        const float mn0 = fmaxf(mr0, mx0), mn1 = fmaxf(mr1, mx1);
        const float c0 = __expf(mr0 - mn0), c1 = __expf(mr1 - mn1);
        mr0 = mn0; mr1 = mn1;

        float s0 = 0.f, s1 = 0.f;
        #pragma unroll
        for (int ni = 0; ni < 8; ni++) {
            float p0 = __expf(S[ni][0] - mn0);
            float p1 = __expf(S[ni][1] - mn0);
            float p2 = __expf(S[ni][2] - mn1);
            float p3 = __expf(S[ni][3] - mn1);
            s0 += p0 + p1;
            s1 += p2 + p3;
            S[ni][0] = __uint_as_float(f2tf(p0));
            S[ni][1] = __uint_as_float(f2tf(p1));
            S[ni][2] = __uint_as_float(f2tf(p2));
            S[ni][3] = __uint_as_float(f2tf(p3));
        }
        s0 += __shfl_xor_sync(0xffffffffu, s0, 1);
        s0 += __shfl_xor_sync(0xffffffffu, s0, 2);
        s1 += __shfl_xor_sync(0xffffffffu, s1, 1);
        s1 += __shfl_xor_sync(0xffffffffu, s1, 2);
        lr0 = lr0 * c0 + s0;
        lr1 = lr1 * c1 + s1;
        #pragma unroll
        for (int ni = 0; ni < 8; ni++) {
            O[ni][0] *= c0; O[ni][1] *= c0;
            O[ni][2] *= c1; O[ni][3] *= c1;
        }

        // O += P @ V (sigma-permuted Vt: C-frag reused as A-frag, no shuffles)
        #pragma unroll
        for (int ks = 0; ks < 8; ks++) {
            unsigned a[4];
            a[0] = __float_as_uint(S[ks][0]);
            a[1] = __float_as_uint(S[ks][2]);
            a[2] = __float_as_uint(S[ks][1]);
            a[3] = __float_as_uint(S[ks][3]);
            #pragma unroll
            for (int ni = 0; ni < 8; ni++) {
                unsigned b0 = Vt[(8 * ni + g) * 68 + 8 * ks + tg];
                unsigned b1 = Vt[(8 * ni + g) * 68 + 8 * ks + tg + 4];
                mma_tf32(O[ni], a, b0, b1);
            }
        }

        CP_WAIT0();        // K(t+1), V(t+1) landed (overlapped with compute)
        __syncthreads();
    }

    // Normalize + store as tf32 bits (same rna cvt O-proj formerly did at load)
    const float inv0 = 1.f / lr0, inv1 = 1.f / lr1;
    const int r0 = q0 + 16 * w + g;
    float* op0 = out + ((size_t)(b * cS + r0)) * cD + h * cDK;
    float* op1 = op0 + (size_t)8 * cD;
    #pragma unroll
    for (int ni = 0; ni < 8; ni++) {
        float2 o0 = {__uint_as_float(f2tf(O[ni][0] * inv0)),
                     __uint_as_float(f2tf(O[ni][1] * inv0))};
        float2 o1 = {__uint_as_float(f2tf(O[ni][2] * inv1)),
                     __uint_as_float(f2tf(O[ni][3] * inv1))};
        *reinterpret_cast<float2*>(op0 + 8 * ni + 2 * tg) = o0;
        *reinterpret_cast<float2*>(op1 + 8 * ni + 2 * tg) = o1;
    }
}

// ---------------------------------------------------------------------------
// Launch
// ---------------------------------------------------------------------------
extern "C" void kernel_launch(void* const* d_in, const int* in_sizes, int n_in,
                              void* d_out, int out_size) {
    const float* q  = (const float*)d_in[0];
    const float* k  = (const float*)d_in[1];
    const float* v  = (const float*)d_in[2];
    const float* Wq = (const float*)d_in[4];
    const float* bq = (const float*)d_in[5];
    const float* Wk = (const float*)d_in[6];
    const float* bk = (const float*)d_in[7];
    const float* Wv = (const float*)d_in[8];
    const float* bv = (const float*)d_in[9];
    const float* Wo = (const float*)d_in[10];
    const float* bo = (const float*)d_in[11];
    float* out = (float*)d_out;

    float *qh, *kh, *vh, *att;
    unsigned *qr, *kr, *vr, *wq, *wk, *wv, *wo;
    cudaGetSymbolAddress((void**)&qh,  g_qh);
    cudaGetSymbolAddress((void**)&kh,  g_kh);
    cudaGetSymbolAddress((void**)&vh,  g_vh);
    cudaGetSymbolAddress((void**)&att, g_att);
    cudaGetSymbolAddress((void**)&qr,  g_qr);
    cudaGetSymbolAddress((void**)&kr,  g_kr);
    cudaGetSymbolAddress((void**)&vr,  g_vr);
    cudaGetSymbolAddress((void**)&wq,  g_wq);
    cudaGetSymbolAddress((void**)&wk,  g_wk);
    cudaGetSymbolAddress((void**)&wv,  g_wv);
    cudaGetSymbolAddress((void**)&wo,  g_wo);

    cudaFuncSetAttribute(attn_mma, cudaFuncAttributeMaxDynamicSharedMemorySize,
                         ATTN_SMEM_BYTES);

    // Pre-round inputs/weights to tf32 bits (rna; same cvt, relocated)
    auto rnd = [](const float* s, unsigned* d, int n) {
        rnd_tf32_kernel<<<(n / 4 + 255) / 256, 256>>>(
            (const float4*)s, (uint4*)d, n / 4);
    };
    rnd(q,  qr, cM * cD);
    rnd(k,  kr, cM * cD);
    rnd(v,  vr, cM * cD);
    rnd(Wq, wq, cD * cD);
    rnd(Wk, wk, cD * cNKV);
    rnd(Wv, wv, cD * cNKV);
    rnd(Wo, wo, cD * cD);

    // Projections: tf32-rounded outputs; Q pre-scaled by 1/sqrt(dk)=0.125
    gemm_mma_async<<<dim3(cD   / 128, cM / 128), 256>>>(qr, wq, bq, qh, cM, cD,   cD, 0.125f, 1);
    gemm_mma_async<<<dim3(cNKV / 128, cM / 128), 256>>>(kr, wk, bk, kh, cM, cNKV, cD, 1.0f,   1);
    gemm_mma_async<<<dim3(cNKV / 128, cM / 128), 256>>>(vr, wv, bv, vh, cM, cNKV, cD, 1.0f,   1);

    attn_mma<<<dim3(cS / 64, cH, cB), 128, ATTN_SMEM_BYTES>>>(qh, kh, vh, att);

    // Output projection: att already tf32 bits; plain fp32 output
    gemm_mma_async<<<dim3(cD / 128, cM / 128), 256>>>(
        (const unsigned*)att, wo, bo, out, cM, cD, cD, 1.0f, 0);
}